// round 3
// baseline (speedup 1.0000x reference)
#include <cuda_runtime.h>
#include <cstdint>

// GatherBlock: out[m, :, :, :] = x[b[m], :, yb[m]*16 : yb[m]*16+16, xb[m]*16 : xb[m]*16+16]
// x: (8, 64, 256, 256) fp32, indices: (1024, 3) int32, out: (1024, 64, 16, 16) fp32.
//
// R3: split each m across 4 CTAs (grid=4096, 16KiB per CTA) so the work
// distributor can dynamically balance SMs — with grid=1024 we had a single
// wave of 6-7 fixed CTAs/SM and the kernel ended on the slowest SM's tail
// (DRAM stuck at 57% with nothing saturated). Keep evict-first streaming
// stores (L2 stays full of x for duplicate-tile read hits) and MLP_p1=4.

static constexpr int C = 64;
static constexpr int H = 256;
static constexpr int W = 256;
static constexpr int BH = 16;
static constexpr int BW = 16;
static constexpr int CHW = C * H * W;      // 4194304
static constexpr int HW = H * W;           // 65536
static constexpr int VEC_PER_M = C * BH * BW / 4;   // 4096 float4 per output block
static constexpr int SPLIT = 4;                     // CTAs per m
static constexpr int VEC_PER_CTA = VEC_PER_M / SPLIT; // 1024 float4 per CTA

__global__ __launch_bounds__(256, 8)
void gather_block_kernel(const float* __restrict__ x,
                         const int* __restrict__ idx,
                         float4* __restrict__ out)
{
    const int m = blockIdx.x >> 2;        // which output block
    const int q = blockIdx.x & 3;         // which quarter of it

    const int b  = idx[3 * m + 0];
    const int yb = idx[3 * m + 1];
    const int xb = idx[3 * m + 2];

    // base of the gathered tile: x[b, 0, yb*16, xb*16]
    const float* src = x + (size_t)b * CHW + (size_t)(yb * BH) * W + (size_t)(xb * BW);
    float4* dst = out + (size_t)m * VEC_PER_M;

    const int t = threadIdx.x;
    const int v0 = q * VEC_PER_CTA + t;   // starting float4 index within the block

    // v in [0, 4096): c = v>>6, row i = (v>>2)&15, j-vector = v&3.
    float4 r[4];
#pragma unroll
    for (int k = 0; k < 4; k++) {
        const int v = v0 + k * 256;
        const int c = v >> 6;
        const int i = (v >> 2) & 15;
        const int j = v & 3;
        const float4* s = reinterpret_cast<const float4*>(
            src + (size_t)c * HW + (size_t)i * W) + j;
        r[k] = *s;
    }
#pragma unroll
    for (int k = 0; k < 4; k++) {
        __stcs(dst + v0 + k * 256, r[k]);
    }
}

extern "C" void kernel_launch(void* const* d_in, const int* in_sizes, int n_in,
                              void* d_out, int out_size)
{
    const float* x  = (const float*)d_in[0];
    const int* idx  = (const int*)d_in[1];
    float4* out     = (float4*)d_out;

    const int M = in_sizes[1] / 3;  // 1024
    gather_block_kernel<<<M * SPLIT, 256>>>(x, idx, out);
}